// round 6
// baseline (speedup 1.0000x reference)
#include <cuda_runtime.h>
#include <cuda_fp16.h>
#include <cstdint>
#include <cstddef>

// Problem dims
#define BATCH 512
#define ICAPS 1152
#define DDIM  8
#define JCAPS 10
#define CDIM  16

// Config: thread = (r = i-row 0..127, b = batch 0..1); 8 warps; 2 CTAs/SM
#define TPB  256
#define BPC  2
#define ROWS 128
#define NRD  9

// Shared layout (u32/float units). x_hat rows (2i+b) x 8 u32, swizzle k^((r>>1)&7)
#define OFF_XH  0
#define XH_U32  (ICAPS * BPC * 8)        // 18432
#define OFF_RED XH_U32                   // [8 warps][2 b][17] = 272
#define OFF_TOT (OFF_RED + 272)          // 18704 : [2][16]
#define OFF_ZT  (OFF_TOT + 32)           // 18736 : [2] (+2 pad)
#define OFF_V   (OFF_ZT + 4)             // 18740 : [2][16]
#define SMEMF   (OFF_V + 32)             // 18772 floats = 75088 B

__global__ void __launch_bounds__(TPB, 2)
digitcaps_kernel(const float* __restrict__ x,
                 const float* __restrict__ W,
                 float* __restrict__ out)
{
    extern __shared__ float sm[];
    unsigned* xhb = reinterpret_cast<unsigned*>(sm + OFF_XH);

    const int tid  = threadIdx.x;
    const int j    = blockIdx.x % JCAPS;
    const int bg   = blockIdx.x / JCAPS;
    const int b    = tid & 1;
    const int r    = tid >> 1;               // 0..127
    const int sw   = (tid >> 2) & 7;         // swizzle key
    const int lane = tid & 31;
    const int warp = tid >> 5;

    const float* Wj = W + (size_t)j * ICAPS * (DDIM * CDIM);
    const float* xg = x + ((size_t)bg * BPC + b) * ICAPS * DDIM;

    // Prefetch x row 0
    float4 xa = *reinterpret_cast<const float4*>(xg + (size_t)r * DDIM);
    float4 xb = *reinterpret_cast<const float4*>(xg + (size_t)r * DDIM + 4);

    float S0[16];
    #pragma unroll
    for (int c = 0; c < 16; c++) S0[c] = 0.f;

    // ---- Build: 9 rounds, NO barriers, W streamed from L2 ----
    #pragma unroll 1
    for (int rd = 0; rd < NRD; rd++) {
        const int i = rd * ROWS + r;
        float xv[8] = {xa.x, xa.y, xa.z, xa.w, xb.x, xb.y, xb.z, xb.w};
        if (rd + 1 < NRD) {
            const float* xp = xg + (size_t)((rd + 1) * ROWS + r) * DDIM;
            xa = *reinterpret_cast<const float4*>(xp);
            xb = *reinterpret_cast<const float4*>(xp + 4);
        }

        const float4* wr = reinterpret_cast<const float4*>(Wj + (size_t)i * (DDIM * CDIM));

        float acc[16];
        #pragma unroll
        for (int c = 0; c < 16; c++) acc[c] = 0.f;

        #pragma unroll
        for (int d = 0; d < 8; d++) {
            float4 w0 = wr[d * 4 + 0];
            float4 w1 = wr[d * 4 + 1];
            float4 w2 = wr[d * 4 + 2];
            float4 w3 = wr[d * 4 + 3];
            float xs = xv[d];
            acc[0]  = fmaf(xs, w0.x, acc[0]);
            acc[1]  = fmaf(xs, w0.y, acc[1]);
            acc[2]  = fmaf(xs, w0.z, acc[2]);
            acc[3]  = fmaf(xs, w0.w, acc[3]);
            acc[4]  = fmaf(xs, w1.x, acc[4]);
            acc[5]  = fmaf(xs, w1.y, acc[5]);
            acc[6]  = fmaf(xs, w1.z, acc[6]);
            acc[7]  = fmaf(xs, w1.w, acc[7]);
            acc[8]  = fmaf(xs, w2.x, acc[8]);
            acc[9]  = fmaf(xs, w2.y, acc[9]);
            acc[10] = fmaf(xs, w2.z, acc[10]);
            acc[11] = fmaf(xs, w2.w, acc[11]);
            acc[12] = fmaf(xs, w3.x, acc[12]);
            acc[13] = fmaf(xs, w3.y, acc[13]);
            acc[14] = fmaf(xs, w3.z, acc[14]);
            acc[15] = fmaf(xs, w3.w, acc[15]);
        }

        // Store x_hat fp16 (own rows only -> no barrier), fold iter-0 sum
        unsigned* xrow = xhb + ((size_t)(2 * i + b) << 3);
        #pragma unroll
        for (int k = 0; k < 8; k++) {
            __half2 h = __floats2half2_rn(acc[2 * k], acc[2 * k + 1]);
            xrow[k ^ sw] = *reinterpret_cast<unsigned*>(&h);
            S0[2 * k]     += acc[2 * k];
            S0[2 * k + 1] += acc[2 * k + 1];
        }
    }

    // ---- Routing: 3 iterations; x_hat read back from own smem rows ----
    float* red = sm + OFF_RED;
    float* tot = sm + OFF_TOT;
    float* zt  = sm + OFF_ZT;
    float* vsm = sm + OFF_V;
    float lg[NRD];

    #pragma unroll
    for (int it = 0; it < 3; it++) {
        float S[16];
        float Zp;

        if (it == 0) {
            #pragma unroll
            for (int c = 0; c < 16; c++) S[c] = S0[c];
            Zp = (float)NRD;                   // b=0 -> uniform softmax
        } else {
            #pragma unroll
            for (int c = 0; c < 16; c++) S[c] = 0.f;
            Zp = 0.f;
            float vv[16];
            #pragma unroll
            for (int c = 0; c < 16; c++) vv[c] = vsm[b * 16 + c];

            #pragma unroll
            for (int rd = 0; rd < NRD; rd++) {
                const unsigned* xrow = xhb + ((size_t)(2 * (rd * ROWS + r) + b) << 3);
                float xf[16];
                #pragma unroll
                for (int k = 0; k < 8; k++) {
                    unsigned u = xrow[k ^ sw];
                    __half2 h = *reinterpret_cast<__half2*>(&u);
                    float2 f = __half22float2(h);
                    xf[2 * k] = f.x; xf[2 * k + 1] = f.y;
                }
                float a = 0.f;
                #pragma unroll
                for (int c = 0; c < 16; c++) a = fmaf(vv[c], xf[c], a);
                float nb;
                if (it == 1) { nb = a; lg[rd] = nb; }
                else         { nb = lg[rd] + a; }
                float e = __expf(nb);          // |nb| small: un-normalized softmax exact
                Zp += e;
                #pragma unroll
                for (int c = 0; c < 16; c++) S[c] = fmaf(e, xf[c], S[c]);
            }
        }

        // Warp reduce over the 16 same-b lanes (b = lane bit 0)
        #pragma unroll
        for (int m = 2; m < 32; m <<= 1) {
            #pragma unroll
            for (int c = 0; c < 16; c++)
                S[c] += __shfl_xor_sync(0xffffffffu, S[c], m);
            Zp += __shfl_xor_sync(0xffffffffu, Zp, m);
        }
        {
            const int cidx = lane >> 1;        // 0..15
            float* rp = red + (warp * 2 + b) * 17;
            rp[cidx] = S[cidx];
            if (lane < 2) rp[16] = Zp;         // lane == b
        }
        __syncthreads();

        // Cross-warp reduction (8 warps)
        if (tid < 32) {
            const int bb = tid & 1, c = tid >> 1;
            float s = 0.f;
            #pragma unroll
            for (int w2 = 0; w2 < 8; w2++)
                s += red[(w2 * 2 + bb) * 17 + c];
            tot[bb * 16 + c] = s;
        } else if (tid < 34) {
            const int bb = tid - 32;
            float z = 0.f;
            #pragma unroll
            for (int w2 = 0; w2 < 8; w2++)
                z += red[(w2 * 2 + bb) * 17 + 16];
            zt[bb] = z;
        }
        __syncthreads();

        // squash per batch
        if (tid < BPC) {
            const int bb = tid;
            float inv = 1.f / zt[bb];
            float sv[16], n2 = 0.f;
            #pragma unroll
            for (int c = 0; c < 16; c++) {
                sv[c] = tot[bb * 16 + c] * inv;
                n2 += sv[c] * sv[c];
            }
            float nr = sqrtf(n2);
            float coef = (n2 / (1.f + n2)) / (nr + 1e-7f);
            #pragma unroll
            for (int c = 0; c < 16; c++) vsm[bb * 16 + c] = coef * sv[c];
        }
        __syncthreads();
    }

    // ---- Output (B, J, C) ----
    if (tid < 32) {
        const int bb = tid >> 4, c = tid & 15;
        out[((size_t)(bg * BPC + bb) * JCAPS + j) * CDIM + c] = vsm[bb * 16 + c];
    }
}

extern "C" void kernel_launch(void* const* d_in, const int* in_sizes, int n_in,
                              void* d_out, int out_size)
{
    const float* x = (const float*)d_in[0];
    const float* W = (const float*)d_in[1];
    if (n_in >= 2 &&
        in_sizes[0] == JCAPS * ICAPS * DDIM * CDIM &&
        in_sizes[1] == BATCH * ICAPS * DDIM) {
        const float* t = x; x = W; W = t;
    }
    float* out = (float*)d_out;

    cudaFuncSetAttribute(digitcaps_kernel,
                         cudaFuncAttributeMaxDynamicSharedMemorySize,
                         SMEMF * (int)sizeof(float));

    dim3 grid((BATCH / BPC) * JCAPS);   // 2560 CTAs, 2 co-resident/SM
    digitcaps_kernel<<<grid, TPB, SMEMF * sizeof(float)>>>(x, W, out);
}

// round 7
// speedup vs baseline: 1.5285x; 1.5285x over previous
#include <cuda_runtime.h>
#include <cuda_fp16.h>
#include <cstdint>
#include <cstddef>

// Problem dims
#define BATCH 512
#define ICAPS 1152
#define DDIM  8
#define JCAPS 10
#define CDIM  16

// Config: thread = (r = row-in-round 0..63, h = channel half 0..1, b = batch 0..1)
//   tid: b = bit0, h = bit1, r = bits 2..7. 8 warps, 2 CTAs/SM.
#define TPB  256
#define BPC  2
#define ROWS 64
#define NRD  18            // 1152 / 64
#define WRS  132           // W smem row stride (128+4): LDS at 2-wavefront floor
#define WSZ  (ROWS * WRS)  // 8448 floats = 33792 B (single buffer)

// Shared layout (float/u32 units)
#define OFF_W   0
#define OFF_XH  WSZ                      // x_hat u32[(2i+b)*8 + k^sw]
#define XH_U32  (ICAPS * BPC * 8)        // 18432
#define OFF_RED (OFF_XH + XH_U32)        // 26880 : [8 warps][4 grp][8]
#define OFF_RZ  (OFF_RED + 256)          // 27136 : [8 warps][2 b]
#define OFF_TOT (OFF_RZ + 16)            // 27152 : [2][16]
#define OFF_ZT  (OFF_TOT + 32)           // 27184 : [2] (+2 pad)
#define OFF_V   (OFF_ZT + 4)             // 27188 : [2][16]
#define SMEMF   (OFF_V + 32)             // 27220 floats = 108880 B

__device__ __forceinline__ void cp16(float* dst, const float* src) {
    unsigned s = (unsigned)__cvta_generic_to_shared(dst);
    asm volatile("cp.async.cg.shared.global [%0], [%1], 16;" :: "r"(s), "l"(src));
}

__global__ void __launch_bounds__(TPB, 2)
digitcaps_kernel(const float* __restrict__ x,
                 const float* __restrict__ W,
                 float* __restrict__ out)
{
    extern __shared__ float sm[];
    unsigned* xhb = reinterpret_cast<unsigned*>(sm + OFF_XH);

    const int tid  = threadIdx.x;
    const int j    = blockIdx.x % JCAPS;
    const int bg   = blockIdx.x / JCAPS;
    const int b    = tid & 1;
    const int h    = (tid >> 1) & 1;
    const int r    = tid >> 2;              // 0..63
    const int sw   = (r >> 1) & 3;          // x_hat swizzle key (stays within h-half)
    const int lane = tid & 31;
    const int warp = tid >> 5;

    const float* Wj = W + (size_t)j * ICAPS * (DDIM * CDIM);
    const float* xg = x + ((size_t)bg * BPC + b) * ICAPS * DDIM;

    // ---- Prologue: stage W round 0 (coalesced cp.async), prefetch x row 0 ----
    #pragma unroll
    for (int k = 0; k < 8; k++) {
        int idx = k * TPB + tid;            // 2048 float4 chunks
        cp16(sm + OFF_W + (idx >> 5) * WRS + (idx & 31) * 4, Wj + (size_t)idx * 4);
    }
    asm volatile("cp.async.commit_group;");

    float4 xa = *reinterpret_cast<const float4*>(xg + (size_t)r * DDIM);
    float4 xb = *reinterpret_cast<const float4*>(xg + (size_t)r * DDIM + 4);

    float S0[8];                            // iter-0 S for this thread's 8 channels
    #pragma unroll
    for (int c = 0; c < 8; c++) S0[c] = 0.f;

    // ---- Build: 18 rounds, single W buffer ----
    #pragma unroll 1
    for (int rd = 0; rd < NRD; rd++) {
        asm volatile("cp.async.wait_group 0;");
        __syncthreads();                    // W[rd] visible

        const int i = rd * ROWS + r;
        float xv[8] = {xa.x, xa.y, xa.z, xa.w, xb.x, xb.y, xb.z, xb.w};
        if (rd + 1 < NRD) {
            const float* xp = xg + (size_t)((rd + 1) * ROWS + r) * DDIM;
            xa = *reinterpret_cast<const float4*>(xp);
            xb = *reinterpret_cast<const float4*>(xp + 4);
        }

        // This thread's 8 channels: global c = 8h + 0..7 -> row words d*16 + 8h ..
        const float* wrow = sm + OFF_W + r * WRS + h * 8;
        float acc[8];
        #pragma unroll
        for (int c = 0; c < 8; c++) acc[c] = 0.f;

        #pragma unroll
        for (int d = 0; d < 8; d++) {
            const float4* wp = reinterpret_cast<const float4*>(wrow + d * 16);
            float4 w0 = wp[0], w1 = wp[1];
            float xs = xv[d];
            acc[0] = fmaf(xs, w0.x, acc[0]);
            acc[1] = fmaf(xs, w0.y, acc[1]);
            acc[2] = fmaf(xs, w0.z, acc[2]);
            acc[3] = fmaf(xs, w0.w, acc[3]);
            acc[4] = fmaf(xs, w1.x, acc[4]);
            acc[5] = fmaf(xs, w1.y, acc[5]);
            acc[6] = fmaf(xs, w1.z, acc[6]);
            acc[7] = fmaf(xs, w1.w, acc[7]);
        }

        // Store x_hat fp16 (own words only: (4h+kk)^sw), fold iter-0 sum
        unsigned* xrow = xhb + ((size_t)(2 * i + b) << 3);
        #pragma unroll
        for (int kk = 0; kk < 4; kk++) {
            __half2 hh = __floats2half2_rn(acc[2 * kk], acc[2 * kk + 1]);
            xrow[(4 * h + kk) ^ sw] = *reinterpret_cast<unsigned*>(&hh);
            S0[2 * kk]     += acc[2 * kk];
            S0[2 * kk + 1] += acc[2 * kk + 1];
        }

        __syncthreads();                    // all reads of W[rd] done
        if (rd + 1 < NRD) {
            const float* wsrc = Wj + (size_t)(rd + 1) * ROWS * (DDIM * CDIM);
            #pragma unroll
            for (int k = 0; k < 8; k++) {
                int idx = k * TPB + tid;
                cp16(sm + OFF_W + (idx >> 5) * WRS + (idx & 31) * 4, wsrc + (size_t)idx * 4);
            }
            asm volatile("cp.async.commit_group;");
        }
    }

    // ---- Routing: 3 iterations ----
    float* red = sm + OFF_RED;
    float* rz  = sm + OFF_RZ;
    float* tot = sm + OFF_TOT;
    float* zt  = sm + OFF_ZT;
    float* vsm = sm + OFF_V;
    float lg[NRD];                          // fully-unrolled static indexing -> registers

    #pragma unroll
    for (int it = 0; it < 3; it++) {
        float S[8];
        float Zp;

        if (it == 0) {
            #pragma unroll
            for (int c = 0; c < 8; c++) S[c] = S0[c];
            Zp = (float)NRD;                // b=0 -> uniform softmax; 18 rows per thread
        } else {
            #pragma unroll
            for (int c = 0; c < 8; c++) S[c] = 0.f;
            Zp = 0.f;
            float vv[8];
            #pragma unroll
            for (int c = 0; c < 8; c++) vv[c] = vsm[b * 16 + h * 8 + c];

            #pragma unroll
            for (int rd = 0; rd < NRD; rd++) {
                const unsigned* xrow = xhb + ((size_t)(2 * (rd * ROWS + r) + b) << 3);
                float xf[8];
                #pragma unroll
                for (int kk = 0; kk < 4; kk++) {
                    unsigned u = xrow[(4 * h + kk) ^ sw];
                    __half2 hh = *reinterpret_cast<__half2*>(&u);
                    float2 f = __half22float2(hh);
                    xf[2 * kk] = f.x; xf[2 * kk + 1] = f.y;
                }
                float a = 0.f;
                #pragma unroll
                for (int c = 0; c < 8; c++) a = fmaf(vv[c], xf[c], a);
                a += __shfl_xor_sync(0xffffffffu, a, 2);   // combine channel halves
                float nb;
                if (it == 1) { nb = a; lg[rd] = nb; }
                else         { nb = lg[rd] + a; }
                float e = __expf(nb);       // |nb| small: un-normalized softmax exact
                Zp += e;
                #pragma unroll
                for (int c = 0; c < 8; c++) S[c] = fmaf(e, xf[c], S[c]);
            }
        }

        // Warp reduce over r-lanes (bits 2..4)
        #pragma unroll
        for (int m = 4; m < 32; m <<= 1) {
            #pragma unroll
            for (int c = 0; c < 8; c++)
                S[c] += __shfl_xor_sync(0xffffffffu, S[c], m);
            Zp += __shfl_xor_sync(0xffffffffu, Zp, m);
        }
        // All lanes of the same (b,h) class hold the class sum; store cooperatively:
        // lane writes element (lane>>2) of group (lane&3) -> 32 distinct banks
        red[(warp * 4 + (lane & 3)) * 8 + (lane >> 2)] =
            __shfl_sync(0xffffffffu, S[lane >> 2], (lane & 3) + ((lane >> 2) << 2) & 31);
        // ^ careful: simpler exact version below overwrites via own-class store
        if (lane < 4)
            #pragma unroll
            for (int c = 0; c < 8; c++)
                red[(warp * 4 + lane) * 8 + c] = S[c];     // lane = b + 2h class id
        if (lane < 2) rz[warp * 2 + b] = Zp;               // h=0 lanes: lane == b
        __syncthreads();

        // Cross-warp reduction: 32 S-totals + 2 Z
        if (tid < 32) {
            const int bb = tid & 1, c = tid >> 1;          // c = h*8 + cc
            const int grp = bb + 2 * (c >> 3);
            float s = 0.f;
            #pragma unroll
            for (int w2 = 0; w2 < 8; w2++)
                s += red[(w2 * 4 + grp) * 8 + (c & 7)];
            tot[bb * 16 + c] = s;
        } else if (tid < 34) {
            const int bb = tid - 32;
            float z = 0.f;
            #pragma unroll
            for (int w2 = 0; w2 < 8; w2++)
                z += rz[w2 * 2 + bb];
            zt[bb] = z;
        }
        __syncthreads();

        if (tid < BPC) {
            const int bb = tid;
            float inv = 1.f / zt[bb];
            float sv[16], n2 = 0.f;
            #pragma unroll
            for (int c = 0; c < 16; c++) {
                sv[c] = tot[bb * 16 + c] * inv;
                n2 += sv[c] * sv[c];
            }
            float nr = sqrtf(n2);
            float coef = (n2 / (1.f + n2)) / (nr + 1e-7f);
            #pragma unroll
            for (int c = 0; c < 16; c++) vsm[bb * 16 + c] = coef * sv[c];
        }
        __syncthreads();
    }

    // ---- Output (B, J, C) ----
    if (tid < 32) {
        const int bb = tid >> 4, c = tid & 15;
        out[((size_t)(bg * BPC + bb) * JCAPS + j) * CDIM + c] = vsm[bb * 16 + c];
    }
}

extern "C" void kernel_launch(void* const* d_in, const int* in_sizes, int n_in,
                              void* d_out, int out_size)
{
    const float* x = (const float*)d_in[0];
    const float* W = (const float*)d_in[1];
    if (n_in >= 2 &&
        in_sizes[0] == JCAPS * ICAPS * DDIM * CDIM &&
        in_sizes[1] == BATCH * ICAPS * DDIM) {
        const float* t = x; x = W; W = t;
    }
    float* out = (float*)d_out;

    cudaFuncSetAttribute(digitcaps_kernel,
                         cudaFuncAttributeMaxDynamicSharedMemorySize,
                         SMEMF * (int)sizeof(float));

    dim3 grid((BATCH / BPC) * JCAPS);   // 2560 CTAs, 2 co-resident per SM
    digitcaps_kernel<<<grid, TPB, SMEMF * sizeof(float)>>>(x, W, out);
}

// round 8
// speedup vs baseline: 1.7529x; 1.1468x over previous
#include <cuda_runtime.h>
#include <cuda_fp16.h>
#include <cstdint>
#include <cstddef>

// Problem dims
#define BATCH 512
#define ICAPS 1152
#define DDIM  8
#define JCAPS 10
#define CDIM  16

// Config: thread = (b = tid&3, h = bit2, r = tid>>3 in 0..63); 16 warps, 1 CTA/SM
#define TPB  512
#define BPC  4
#define ROWS 64
#define NRD  18            // 1152 / 64
#define WRS  132           // W smem row stride (128+4 floats)
#define WSZ1 (ROWS * WRS)  // 8448 floats per W buffer

// Shared layout (float/u32 units)
#define OFF_W   0                          // 2 buffers
#define OFF_XH  (2 * WSZ1)                 // 16896
#define XH_U32  (ICAPS * BPC * 8)          // 36864 u32 (fp16 x_hat)
#define OFF_RED (OFF_XH + XH_U32)          // 53760 : [16 warps][8 class][8]
#define OFF_RZ  (OFF_RED + 16 * 64)        // 54784 : [16 warps][4 b]
#define OFF_TOT (OFF_RZ + 64)              // 54848 : [4][16]
#define OFF_ZT  (OFF_TOT + 64)             // 54912 : [4]
#define OFF_V   (OFF_ZT + 4)               // 54916 : v    [4][16]
#define OFF_VS  (OFF_V + 64)               // 54980 : vsum [4][16]
#define SMEMF   (OFF_VS + 64)              // 55044 floats = 220176 B

__device__ __forceinline__ void cp16(float* dst, const float* src) {
    unsigned s = (unsigned)__cvta_generic_to_shared(dst);
    asm volatile("cp.async.cg.shared.global [%0], [%1], 16;" :: "r"(s), "l"(src));
}

__global__ void __launch_bounds__(TPB, 1)
digitcaps_kernel(const float* __restrict__ x,
                 const float* __restrict__ W,
                 float* __restrict__ out)
{
    extern __shared__ float sm[];
    unsigned* xhb = reinterpret_cast<unsigned*>(sm + OFF_XH);

    const int tid  = threadIdx.x;
    const int j    = blockIdx.x % JCAPS;
    const int bg   = blockIdx.x / JCAPS;
    const int b    = tid & 3;
    const int h    = (tid >> 2) & 1;
    const int r    = tid >> 3;             // 0..63
    const int rl   = r & 3;                // swizzle key
    const int lane = tid & 31;
    const int warp = tid >> 5;

    const float* Wj = W + (size_t)j * ICAPS * (DDIM * CDIM);
    const float* xg = x + ((size_t)bg * BPC + b) * ICAPS * DDIM;

    // ---- Prologue: stage W round 0 into buffer 0, prefetch x row 0 ----
    #pragma unroll
    for (int k = 0; k < 4; k++) {          // 2048 float4 chunks / 512 threads
        int idx = k * TPB + tid;
        cp16(sm + OFF_W + (idx >> 5) * WRS + (idx & 31) * 4, Wj + (size_t)idx * 4);
    }
    asm volatile("cp.async.commit_group;");

    float4 xa = *reinterpret_cast<const float4*>(xg + (size_t)r * DDIM);
    float4 xb = *reinterpret_cast<const float4*>(xg + (size_t)r * DDIM + 4);

    float S0[8];
    #pragma unroll
    for (int c = 0; c < 8; c++) S0[c] = 0.f;

    // ---- Build: 18 rounds, double-buffered W, one sync per round ----
    #pragma unroll 1
    for (int rd = 0; rd < NRD; rd++) {
        asm volatile("cp.async.wait_group 0;");
        __syncthreads();                   // W[rd] ready; all threads past rd-1

        if (rd + 1 < NRD) {                // stage rd+1 into the other buffer
            const float* wsrc = Wj + (size_t)(rd + 1) * ROWS * (DDIM * CDIM);
            float* wd = sm + OFF_W + ((rd + 1) & 1) * WSZ1;
            #pragma unroll
            for (int k = 0; k < 4; k++) {
                int idx = k * TPB + tid;
                cp16(wd + (idx >> 5) * WRS + (idx & 31) * 4, wsrc + (size_t)idx * 4);
            }
            asm volatile("cp.async.commit_group;");
        }

        const int i = rd * ROWS + r;
        float xv[8] = {xa.x, xa.y, xa.z, xa.w, xb.x, xb.y, xb.z, xb.w};
        if (rd + 1 < NRD) {                // prefetch next x (L2-resident)
            const float* xp = xg + (size_t)((rd + 1) * ROWS + r) * DDIM;
            xa = *reinterpret_cast<const float4*>(xp);
            xb = *reinterpret_cast<const float4*>(xp + 4);
        }

        // This thread's 8 channels = global h*8 .. h*8+7
        const float* wrow = sm + OFF_W + (rd & 1) * WSZ1 + r * WRS + h * 8;
        float acc[8];
        #pragma unroll
        for (int c = 0; c < 8; c++) acc[c] = 0.f;

        #pragma unroll
        for (int d = 0; d < 8; d++) {
            const float4* wp = reinterpret_cast<const float4*>(wrow + d * 16);
            float4 w0 = wp[0], w1 = wp[1];
            float xs = xv[d];
            acc[0] = fmaf(xs, w0.x, acc[0]);
            acc[1] = fmaf(xs, w0.y, acc[1]);
            acc[2] = fmaf(xs, w0.z, acc[2]);
            acc[3] = fmaf(xs, w0.w, acc[3]);
            acc[4] = fmaf(xs, w1.x, acc[4]);
            acc[5] = fmaf(xs, w1.y, acc[5]);
            acc[6] = fmaf(xs, w1.z, acc[6]);
            acc[7] = fmaf(xs, w1.w, acc[7]);
        }

        // Store fp16 x_hat (own words, swizzled (4h+kk)^rl -> conflict-free), fold iter-0 sum
        unsigned* xrow = xhb + ((size_t)(i * 4 + b) << 3);
        #pragma unroll
        for (int kk = 0; kk < 4; kk++) {
            __half2 hh = __floats2half2_rn(acc[2 * kk], acc[2 * kk + 1]);
            xrow[(4 * h + kk) ^ rl] = *reinterpret_cast<unsigned*>(&hh);
            S0[2 * kk]     += acc[2 * kk];
            S0[2 * kk + 1] += acc[2 * kk + 1];
        }
        // no trailing sync: next round's top sync protects the buffer being restaged
    }

    // ---- Routing: 3 iterations. Logits are LINEAR in v: b_k = (sum of v_m, m<k) . x_hat
    //      -> no logit storage at all; keep cumulative vsum in smem.
    float* red = sm + OFF_RED;
    float* rz  = sm + OFF_RZ;
    float* tot = sm + OFF_TOT;
    float* zt  = sm + OFF_ZT;
    float* vsm = sm + OFF_V;
    float* vss = sm + OFF_VS;

    #pragma unroll
    for (int it = 0; it < 3; it++) {
        float S[8];
        float Zp;

        if (it == 0) {
            #pragma unroll
            for (int c = 0; c < 8; c++) S[c] = S0[c];
            Zp = (float)NRD;               // b=0 -> uniform softmax; 18 rows/thread
        } else {
            #pragma unroll
            for (int c = 0; c < 8; c++) S[c] = 0.f;
            Zp = 0.f;
            float vv[8];
            #pragma unroll
            for (int c = 0; c < 8; c++) vv[c] = vss[b * 16 + h * 8 + c];

            #pragma unroll 6
            for (int rd = 0; rd < NRD; rd++) {
                const unsigned* xrow = xhb + ((size_t)((rd * ROWS + r) * 4 + b) << 3);
                float xf[8];
                #pragma unroll
                for (int kk = 0; kk < 4; kk++) {
                    unsigned u = xrow[(4 * h + kk) ^ rl];
                    __half2 hh = *reinterpret_cast<__half2*>(&u);
                    float2 f = __half22float2(hh);
                    xf[2 * kk] = f.x; xf[2 * kk + 1] = f.y;
                }
                float a = 0.f;
                #pragma unroll
                for (int c = 0; c < 8; c++) a = fmaf(vv[c], xf[c], a);
                a += __shfl_xor_sync(0xffffffffu, a, 4);   // combine channel halves (h = lane bit 2)
                float e = __expf(a);       // a IS the logit; |a| small -> un-normalized softmax exact
                Zp += e;
                #pragma unroll
                for (int c = 0; c < 8; c++) S[c] = fmaf(e, xf[c], S[c]);
            }
        }

        // Warp reduce over rl lanes (bits 3,4); classes = (b, h) = lanes 0..7
        #pragma unroll
        for (int m = 8; m < 32; m <<= 1) {
            #pragma unroll
            for (int c = 0; c < 8; c++)
                S[c] += __shfl_xor_sync(0xffffffffu, S[c], m);
            Zp += __shfl_xor_sync(0xffffffffu, Zp, m);
        }
        if (lane < 8) {                    // lane = b + 4h
            float* rp = red + warp * 64 + lane * 8;
            #pragma unroll
            for (int c = 0; c < 8; c++) rp[c] = S[c];
        }
        if (lane < 4) rz[warp * 4 + lane] = Zp;   // h=0 classes only (Z duplicated across h)
        __syncthreads();

        // Cross-warp reduction
        if (tid < 64) {
            const int bb = tid & 3, c = tid >> 2;          // c = 0..15
            const int cls = bb + 4 * (c >> 3);
            float s = 0.f;
            #pragma unroll
            for (int w2 = 0; w2 < 16; w2++)
                s += red[w2 * 64 + cls * 8 + (c & 7)];
            tot[bb * 16 + c] = s;
        } else if (tid < 68) {
            const int bb = tid - 64;
            float z = 0.f;
            #pragma unroll
            for (int w2 = 0; w2 < 16; w2++)
                z += rz[w2 * 4 + bb];
            zt[bb] = z;
        }
        __syncthreads();

        // squash per batch; update v and cumulative vsum
        if (tid < BPC) {
            const int bb = tid;
            float inv = 1.f / zt[bb];
            float sv[16], n2 = 0.f;
            #pragma unroll
            for (int c = 0; c < 16; c++) {
                sv[c] = tot[bb * 16 + c] * inv;
                n2 += sv[c] * sv[c];
            }
            float nr = sqrtf(n2);
            float coef = (n2 / (1.f + n2)) / (nr + 1e-7f);
            #pragma unroll
            for (int c = 0; c < 16; c++) {
                float vn = coef * sv[c];
                vsm[bb * 16 + c] = vn;
                vss[bb * 16 + c] = (it == 0) ? vn : (vss[bb * 16 + c] + vn);
            }
        }
        __syncthreads();
    }

    // ---- Output (B, J, C): final v ----
    if (tid < 64) {
        const int bb = tid >> 4, c = tid & 15;
        out[((size_t)(bg * BPC + bb) * JCAPS + j) * CDIM + c] = vsm[bb * 16 + c];
    }
}

extern "C" void kernel_launch(void* const* d_in, const int* in_sizes, int n_in,
                              void* d_out, int out_size)
{
    const float* x = (const float*)d_in[0];
    const float* W = (const float*)d_in[1];
    if (n_in >= 2 &&
        in_sizes[0] == JCAPS * ICAPS * DDIM * CDIM &&
        in_sizes[1] == BATCH * ICAPS * DDIM) {
        const float* t = x; x = W; W = t;
    }
    float* out = (float*)d_out;

    cudaFuncSetAttribute(digitcaps_kernel,
                         cudaFuncAttributeMaxDynamicSharedMemorySize,
                         SMEMF * (int)sizeof(float));

    dim3 grid((BATCH / BPC) * JCAPS);   // 1280 CTAs, 1/SM, minimal W L2 traffic
    digitcaps_kernel<<<grid, TPB, SMEMF * sizeof(float)>>>(x, W, out);
}

// round 9
// speedup vs baseline: 1.9963x; 1.1388x over previous
#include <cuda_runtime.h>
#include <cuda_fp16.h>
#include <cstdint>
#include <cstddef>

// Problem dims
#define BATCH 512
#define ICAPS 1152
#define DDIM  8
#define JCAPS 10
#define CDIM  16

// Config
#define TPB  512
#define BPC  4
#define ROWS 64            // W rows per build round
#define NRD  18            // 1152 / 64
#define NRD2 9             // routing rounds of 128
#define WRS  144           // W smem row stride (floats); WRS/4=36 == 4 mod 8 -> conflict-free LDS.128
#define WSZ1 (ROWS * WRS)  // 9216 floats per W buffer

// Shared layout (float units)
#define OFF_W   0                      // 2 W buffers
#define OFF_XH  (2 * WSZ1)             // 18432 : x_hat u32[(i*4+b)*8 + word], pair-swizzled
#define XH_U32  (ICAPS * BPC * 8)      // 36864
#define OFF_RED (OFF_XH + XH_U32)      // 55296 : shared scratch (build: 16*64, routing: 16*4*17)
#define OFF_TOT (OFF_RED + 1152)       // 56448 : [4][16]
#define OFF_ZT  (OFF_TOT + 64)         // 56512 : [4]
#define OFF_V   (OFF_ZT + 4)           // 56516 : v    [4][16]
#define OFF_VS  (OFF_V + 64)           // 56580 : vsum [4][16]
#define SMEMF   (OFF_VS + 64)          // 56644 floats = 226576 B (< 232448 max)

typedef unsigned long long u64;

__device__ __forceinline__ void cp16(float* dst, const float* src) {
    unsigned s = (unsigned)__cvta_generic_to_shared(dst);
    asm volatile("cp.async.cg.shared.global [%0], [%1], 16;" :: "r"(s), "l"(src));
}
__device__ __forceinline__ u64 pack2(float lo, float hi) {
    u64 r; asm("mov.b64 %0, {%1, %2};" : "=l"(r) : "f"(lo), "f"(hi)); return r;
}
__device__ __forceinline__ void unpack2(u64 v, float& lo, float& hi) {
    asm("mov.b64 {%0, %1}, %2;" : "=f"(lo), "=f"(hi) : "l"(v));
}
__device__ __forceinline__ void ffma2(u64& d, u64 a, u64 b) {
    asm("fma.rn.f32x2 %0, %1, %2, %0;" : "+l"(d) : "l"(a), "l"(b));
}

__global__ void __launch_bounds__(TPB, 1)
digitcaps_kernel(const float* __restrict__ x,
                 const float* __restrict__ W,
                 float* __restrict__ out)
{
    extern __shared__ float sm[];
    unsigned* xhb = reinterpret_cast<unsigned*>(sm + OFF_XH);

    const int tid  = threadIdx.x;
    const int j    = blockIdx.x % JCAPS;
    const int bg   = blockIdx.x / JCAPS;
    const int lane = tid & 31;
    const int warp = tid >> 5;

    // Build-phase thread map: q = channel-quad, bh = batch-half, r = row-in-round
    const int q   = tid & 3;
    const int bh  = (tid >> 2) & 1;
    const int r   = tid >> 3;              // 0..63
    const int rl3 = r & 3;                 // x_hat pair-swizzle key (i&3 == r&3)

    const float* Wj  = W + (size_t)j * ICAPS * (DDIM * CDIM);
    const float* xg0 = x + ((size_t)bg * BPC + bh * 2 + 0) * ICAPS * DDIM;
    const float* xg1 = x + ((size_t)bg * BPC + bh * 2 + 1) * ICAPS * DDIM;

    // ---- Prologue: stage W round 0, prefetch x row 0 (both batches) ----
    #pragma unroll
    for (int k = 0; k < 4; k++) {          // 2048 16B chunks / 512 threads
        int idx = k * TPB + tid;
        cp16(sm + OFF_W + (idx >> 5) * WRS + (idx & 31) * 4, Wj + (size_t)idx * 4);
    }
    asm volatile("cp.async.commit_group;");

    float4 xa0 = *reinterpret_cast<const float4*>(xg0 + (size_t)r * DDIM);
    float4 xb0 = *reinterpret_cast<const float4*>(xg0 + (size_t)r * DDIM + 4);
    float4 xa1 = *reinterpret_cast<const float4*>(xg1 + (size_t)r * DDIM);
    float4 xb1 = *reinterpret_cast<const float4*>(xg1 + (size_t)r * DDIM + 4);

    u64 S0p[4];                            // iter-0 S: 2 batches x 2 ch-pairs (f32x2)
    #pragma unroll
    for (int k = 0; k < 4; k++) S0p[k] = 0ull;

    // ---- Build: 18 rounds, double-buffered W, FFMA2, no broadcast waste ----
    #pragma unroll 1
    for (int rd = 0; rd < NRD; rd++) {
        asm volatile("cp.async.wait_group 0;");
        __syncthreads();                   // W[rd] visible; all past rd-1 buffer

        if (rd + 1 < NRD) {
            const float* wsrc = Wj + (size_t)(rd + 1) * ROWS * (DDIM * CDIM);
            float* wd = sm + OFF_W + ((rd + 1) & 1) * WSZ1;
            #pragma unroll
            for (int k = 0; k < 4; k++) {
                int idx = k * TPB + tid;
                cp16(wd + (idx >> 5) * WRS + (idx & 31) * 4, wsrc + (size_t)idx * 4);
            }
            asm volatile("cp.async.commit_group;");
        }

        const int i = rd * ROWS + r;
        float x0[8] = {xa0.x, xa0.y, xa0.z, xa0.w, xb0.x, xb0.y, xb0.z, xb0.w};
        float x1[8] = {xa1.x, xa1.y, xa1.z, xa1.w, xb1.x, xb1.y, xb1.z, xb1.w};
        if (rd + 1 < NRD) {                // prefetch next x (L2-resident)
            const float* p0 = xg0 + (size_t)((rd + 1) * ROWS + r) * DDIM;
            const float* p1 = xg1 + (size_t)((rd + 1) * ROWS + r) * DDIM;
            xa0 = *reinterpret_cast<const float4*>(p0);
            xb0 = *reinterpret_cast<const float4*>(p0 + 4);
            xa1 = *reinterpret_cast<const float4*>(p1);
            xb1 = *reinterpret_cast<const float4*>(p1 + 4);
        }

        // This thread's 4 channels (q*4..q*4+3) for 2 batches; W as 2 x f32x2 per d
        const float* wrow = sm + OFF_W + (rd & 1) * WSZ1 + r * WRS + q * 4;
        u64 acc0a = 0ull, acc0b = 0ull, acc1a = 0ull, acc1b = 0ull;

        #pragma unroll
        for (int d = 0; d < 8; d++) {
            ulonglong2 w2 = *reinterpret_cast<const ulonglong2*>(wrow + d * 16);
            u64 xs0 = pack2(x0[d], x0[d]);
            u64 xs1 = pack2(x1[d], x1[d]);
            ffma2(acc0a, xs0, w2.x);
            ffma2(acc0b, xs0, w2.y);
            ffma2(acc1a, xs1, w2.x);
            ffma2(acc1b, xs1, w2.y);
        }

        // fold iter-0 sum (exact fp32)
        asm("add.rn.f32x2 %0, %0, %1;" : "+l"(S0p[0]) : "l"(acc0a));
        asm("add.rn.f32x2 %0, %0, %1;" : "+l"(S0p[1]) : "l"(acc0b));
        asm("add.rn.f32x2 %0, %0, %1;" : "+l"(S0p[2]) : "l"(acc1a));
        asm("add.rn.f32x2 %0, %0, %1;" : "+l"(S0p[3]) : "l"(acc1b));

        // store x_hat fp16: pair p (=4ch) at physical pair q^(i&3) of row (i*4+b)
        {
            const int pp = q ^ rl3;
            float lo, hi;
            unsigned w0, w1;
            // batch bh*2+0
            unpack2(acc0a, lo, hi);
            { __half2 h = __floats2half2_rn(lo, hi); w0 = *reinterpret_cast<unsigned*>(&h); }
            unpack2(acc0b, lo, hi);
            { __half2 h = __floats2half2_rn(lo, hi); w1 = *reinterpret_cast<unsigned*>(&h); }
            unsigned base0 = (unsigned)((i * 4 + bh * 2 + 0) * 8 + pp * 2);
            *reinterpret_cast<uint2*>(xhb + base0) = make_uint2(w0, w1);
            // batch bh*2+1
            unpack2(acc1a, lo, hi);
            { __half2 h = __floats2half2_rn(lo, hi); w0 = *reinterpret_cast<unsigned*>(&h); }
            unpack2(acc1b, lo, hi);
            { __half2 h = __floats2half2_rn(lo, hi); w1 = *reinterpret_cast<unsigned*>(&h); }
            unsigned base1 = (unsigned)((i * 4 + bh * 2 + 1) * 8 + pp * 2);
            *reinterpret_cast<uint2*>(xhb + base1) = make_uint2(w0, w1);
        }
    }

    // ---- iter-0 reduction (build thread map) ----
    float* red = sm + OFF_RED;
    float* tot = sm + OFF_TOT;
    float* zt  = sm + OFF_ZT;
    float* vsm = sm + OFF_V;
    float* vss = sm + OFF_VS;

    {
        float s0[8];                       // [bl*4 + cc]: ch q*4+cc, batch bh*2+bl
        unpack2(S0p[0], s0[0], s0[1]);
        unpack2(S0p[1], s0[2], s0[3]);
        unpack2(S0p[2], s0[4], s0[5]);
        unpack2(S0p[3], s0[6], s0[7]);
        #pragma unroll
        for (int m = 8; m < 32; m <<= 1)
            #pragma unroll
            for (int e = 0; e < 8; e++)
                s0[e] += __shfl_xor_sync(0xffffffffu, s0[e], m);
        if (lane < 8) {                    // lane = q + 4*bh
            float* rp = red + warp * 64 + lane * 8;
            #pragma unroll
            for (int e = 0; e < 8; e++) rp[e] = s0[e];
        }
        __syncthreads();

        if (tid < 64) {
            const int bb = tid & 3, c = tid >> 2;
            const int cls = (c >> 2) + 4 * (bb >> 1);      // (q, bh)
            const int ele = (c & 3) + 4 * (bb & 1);        // (cc, bl)
            float s = 0.f;
            #pragma unroll
            for (int w2 = 0; w2 < 16; w2++)
                s += red[w2 * 64 + cls * 8 + ele];
            tot[bb * 16 + c] = s;
        }
        __syncthreads();

        if (tid < BPC) {                   // squash iter 0 (Z = 1152 exactly)
            const int bb = tid;
            const float inv = 1.f / (float)ICAPS;
            float sv[16], n2 = 0.f;
            #pragma unroll
            for (int c = 0; c < 16; c++) {
                sv[c] = tot[bb * 16 + c] * inv;
                n2 += sv[c] * sv[c];
            }
            float nr = sqrtf(n2);
            float coef = (n2 / (1.f + n2)) / (nr + 1e-7f);
            #pragma unroll
            for (int c = 0; c < 16; c++) {
                float vn = coef * sv[c];
                vsm[bb * 16 + c] = vn;
                vss[bb * 16 + c] = vn;     // cumulative v-sum (logits linear in v)
            }
        }
        __syncthreads();
    }

    // ---- Routing iters 1,2: thread = (b = tid&3, r' = tid>>2), 16 ch/thread ----
    const int b2  = tid & 3;
    const int r2  = tid >> 2;              // 0..127
    const int sl3 = r2 & 3;                // pair swizzle (i&3 == r2&3)

    #pragma unroll
    for (int it = 1; it < 3; it++) {
        float S[16];
        #pragma unroll
        for (int c = 0; c < 16; c++) S[c] = 0.f;
        float Zp = 0.f;
        float vv[16];
        #pragma unroll
        for (int c = 0; c < 16; c++) vv[c] = vss[b2 * 16 + c];

        #pragma unroll
        for (int rd = 0; rd < NRD2; rd++) {
            const int i = rd * 128 + r2;
            const unsigned base = (unsigned)((i * 4 + b2) * 8);
            float xf[16];
            #pragma unroll
            for (int qq = 0; qq < 4; qq++) {
                uint2 u = *reinterpret_cast<const uint2*>(xhb + base + (qq ^ sl3) * 2);
                __half2 h0 = *reinterpret_cast<__half2*>(&u.x);
                __half2 h1 = *reinterpret_cast<__half2*>(&u.y);
                float2 f0 = __half22float2(h0);
                float2 f1 = __half22float2(h1);
                xf[qq * 4 + 0] = f0.x; xf[qq * 4 + 1] = f0.y;
                xf[qq * 4 + 2] = f1.x; xf[qq * 4 + 3] = f1.y;
            }
            float a = 0.f;
            #pragma unroll
            for (int c = 0; c < 16; c++) a = fmaf(vv[c], xf[c], a);
            float e = __expf(a);           // a is the logit (vsum . x_hat); |a| small
            Zp += e;
            #pragma unroll
            for (int c = 0; c < 16; c++) S[c] = fmaf(e, xf[c], S[c]);
        }

        // warp reduce over r'-lanes (bits 2..4); classes b2 = lanes 0..3
        #pragma unroll
        for (int m = 4; m < 32; m <<= 1) {
            #pragma unroll
            for (int c = 0; c < 16; c++)
                S[c] += __shfl_xor_sync(0xffffffffu, S[c], m);
            Zp += __shfl_xor_sync(0xffffffffu, Zp, m);
        }
        if (lane < 4) {
            float* rp = red + (warp * 4 + lane) * 17;
            #pragma unroll
            for (int c = 0; c < 16; c++) rp[c] = S[c];
            rp[16] = Zp;
        }
        __syncthreads();

        if (tid < 64) {
            const int bb = tid & 3, c = tid >> 2;
            float s = 0.f;
            #pragma unroll
            for (int w2 = 0; w2 < 16; w2++)
                s += red[(w2 * 4 + bb) * 17 + c];
            tot[bb * 16 + c] = s;
        } else if (tid < 68) {
            const int bb = tid - 64;
            float z = 0.f;
            #pragma unroll
            for (int w2 = 0; w2 < 16; w2++)
                z += red[(w2 * 4 + bb) * 17 + 16];
            zt[bb] = z;
        }
        __syncthreads();

        if (tid < BPC) {
            const int bb = tid;
            float inv = 1.f / zt[bb];
            float sv[16], n2 = 0.f;
            #pragma unroll
            for (int c = 0; c < 16; c++) {
                sv[c] = tot[bb * 16 + c] * inv;
                n2 += sv[c] * sv[c];
            }
            float nr = sqrtf(n2);
            float coef = (n2 / (1.f + n2)) / (nr + 1e-7f);
            #pragma unroll
            for (int c = 0; c < 16; c++) {
                float vn = coef * sv[c];
                vsm[bb * 16 + c] = vn;
                vss[bb * 16 + c] += vn;
            }
        }
        __syncthreads();
    }

    // ---- Output (B, J, C) ----
    if (tid < 64) {
        const int bb = tid >> 4, c = tid & 15;
        out[((size_t)(bg * BPC + bb) * JCAPS + j) * CDIM + c] = vsm[bb * 16 + c];
    }
}

extern "C" void kernel_launch(void* const* d_in, const int* in_sizes, int n_in,
                              void* d_out, int out_size)
{
    const float* x = (const float*)d_in[0];
    const float* W = (const float*)d_in[1];
    if (n_in >= 2 &&
        in_sizes[0] == JCAPS * ICAPS * DDIM * CDIM &&
        in_sizes[1] == BATCH * ICAPS * DDIM) {
        const float* t = x; x = W; W = t;
    }
    float* out = (float*)d_out;

    cudaFuncSetAttribute(digitcaps_kernel,
                         cudaFuncAttributeMaxDynamicSharedMemorySize,
                         SMEMF * (int)sizeof(float));

    dim3 grid((BATCH / BPC) * JCAPS);   // 1280 CTAs
    digitcaps_kernel<<<grid, TPB, SMEMF * sizeof(float)>>>(x, W, out);
}

// round 10
// speedup vs baseline: 2.1020x; 1.0530x over previous
#include <cuda_runtime.h>
#include <cuda_fp16.h>
#include <cstdint>
#include <cstddef>

// Problem dims
#define BATCH 512
#define ICAPS 1152
#define DDIM  8
#define JCAPS 10
#define CDIM  16

// Config (build map: q = tid&3 channel-quad, bh = bit2 batch-half, r = tid>>3)
#define TPB  512
#define BPC  4
#define ROWS 64            // W rows per build round
#define NRD  18            // 1152 / 64
#define NRD2 9             // routing rounds of 128
#define WRSH 72            // W smem row stride in FLOATS (= 144 half = 288B); 72 mod 32 = 8
#define WSZ1 (ROWS * WRSH) // 4608 floats per fp16-W buffer

// Shared layout (float units)
#define OFF_W   0                      // 2 fp16-W buffers
#define OFF_XH  (2 * WSZ1)             // 9216 : x_hat u32[(i*4+b)*8 + word], pair-swizzled
#define XH_U32  (ICAPS * BPC * 8)      // 36864
#define OFF_RED (OFF_XH + XH_U32)      // 46080 : scratch (build 16*64 / routing 16*4*17)
#define OFF_TOT (OFF_RED + 1152)       // 47232 : [4][16]
#define OFF_ZT  (OFF_TOT + 64)         // 47296 : [4]
#define OFF_V   (OFF_ZT + 4)           // 47300 : v    [4][16]
#define OFF_VS  (OFF_V + 64)           // 47364 : vsum [4][16]
#define SMEMF   (OFF_VS + 64)          // 47428 floats = 189712 B

typedef unsigned long long u64;

// fp16 copy of W, filled by convert kernel each launch (sanctioned __device__ scratch)
__device__ __half2 g_Wh[JCAPS * ICAPS * CDIM * DDIM / 2];   // 2.95 MB

__device__ __forceinline__ void cp16(float* dst, const void* src) {
    unsigned s = (unsigned)__cvta_generic_to_shared(dst);
    asm volatile("cp.async.cg.shared.global [%0], [%1], 16;" :: "r"(s), "l"(src));
}
__device__ __forceinline__ u64 pack2(float lo, float hi) {
    u64 r; asm("mov.b64 %0, {%1, %2};" : "=l"(r) : "f"(lo), "f"(hi)); return r;
}
__device__ __forceinline__ void unpack2(u64 v, float& lo, float& hi) {
    asm("mov.b64 {%0, %1}, %2;" : "=f"(lo), "=f"(hi) : "l"(v));
}
__device__ __forceinline__ void ffma2(u64& d, u64 a, u64 b) {
    asm("fma.rn.f32x2 %0, %1, %2, %0;" : "+l"(d) : "l"(a), "l"(b));
}

// ---- Kernel A: W fp32 -> fp16 (same [j][i][d][c] order) ----
__global__ void __launch_bounds__(512, 4)
convert_w_kernel(const float* __restrict__ W)
{
    int i = blockIdx.x * 512 + threadIdx.x;       // float4 index, exact cover
    float4 f = reinterpret_cast<const float4*>(W)[i];
    g_Wh[i * 2 + 0] = __floats2half2_rn(f.x, f.y);
    g_Wh[i * 2 + 1] = __floats2half2_rn(f.z, f.w);
}

// ---- Kernel B: main ----
__global__ void __launch_bounds__(TPB, 1)
digitcaps_kernel(const float* __restrict__ x,
                 float* __restrict__ out)
{
    extern __shared__ float sm[];
    unsigned* xhb = reinterpret_cast<unsigned*>(sm + OFF_XH);

    const int tid  = threadIdx.x;
    const int j    = blockIdx.x % JCAPS;
    const int bg   = blockIdx.x / JCAPS;
    const int lane = tid & 31;
    const int warp = tid >> 5;

    // Build-phase map
    const int q   = tid & 3;
    const int bh  = (tid >> 2) & 1;
    const int r   = tid >> 3;              // 0..63
    const int rl3 = r & 3;                 // x_hat pair-swizzle key

    const __half* Wjh = reinterpret_cast<const __half*>(g_Wh)
                      + (size_t)j * ICAPS * (DDIM * CDIM);
    const float* xg0 = x + ((size_t)bg * BPC + bh * 2 + 0) * ICAPS * DDIM;
    const float* xg1 = x + ((size_t)bg * BPC + bh * 2 + 1) * ICAPS * DDIM;

    // ---- Prologue: stage fp16 W round 0 (1024 16B chunks, 2/thread) ----
    #pragma unroll
    for (int k = 0; k < 2; k++) {
        int idx = k * TPB + tid;
        cp16(sm + OFF_W + (idx >> 4) * WRSH + (idx & 15) * 4, Wjh + (size_t)idx * 8);
    }
    asm volatile("cp.async.commit_group;");

    float4 xa0 = *reinterpret_cast<const float4*>(xg0 + (size_t)r * DDIM);
    float4 xb0 = *reinterpret_cast<const float4*>(xg0 + (size_t)r * DDIM + 4);
    float4 xa1 = *reinterpret_cast<const float4*>(xg1 + (size_t)r * DDIM);
    float4 xb1 = *reinterpret_cast<const float4*>(xg1 + (size_t)r * DDIM + 4);

    u64 S0p[4];
    #pragma unroll
    for (int k = 0; k < 4; k++) S0p[k] = 0ull;

    // ---- Build: 18 rounds, double-buffered fp16 W ----
    #pragma unroll 1
    for (int rd = 0; rd < NRD; rd++) {
        asm volatile("cp.async.wait_group 0;");
        __syncthreads();

        if (rd + 1 < NRD) {
            const __half* wsrc = Wjh + (size_t)(rd + 1) * ROWS * (DDIM * CDIM);
            float* wd = sm + OFF_W + ((rd + 1) & 1) * WSZ1;
            #pragma unroll
            for (int k = 0; k < 2; k++) {
                int idx = k * TPB + tid;
                cp16(wd + (idx >> 4) * WRSH + (idx & 15) * 4, wsrc + (size_t)idx * 8);
            }
            asm volatile("cp.async.commit_group;");
        }

        const int i = rd * ROWS + r;
        float x0[8] = {xa0.x, xa0.y, xa0.z, xa0.w, xb0.x, xb0.y, xb0.z, xb0.w};
        float x1[8] = {xa1.x, xa1.y, xa1.z, xa1.w, xb1.x, xb1.y, xb1.z, xb1.w};
        if (rd + 1 < NRD) {
            const float* p0 = xg0 + (size_t)((rd + 1) * ROWS + r) * DDIM;
            const float* p1 = xg1 + (size_t)((rd + 1) * ROWS + r) * DDIM;
            xa0 = *reinterpret_cast<const float4*>(p0);
            xb0 = *reinterpret_cast<const float4*>(p0 + 4);
            xa1 = *reinterpret_cast<const float4*>(p1);
            xb1 = *reinterpret_cast<const float4*>(p1 + 4);
        }

        // per d: LDS.64 -> 4 fp16 channels -> cvt fp32 -> 4 FFMA2 (2 batches x 2 pairs)
        const float* wrow = sm + OFF_W + (rd & 1) * WSZ1 + r * WRSH + q * 2;
        u64 acc0a = 0ull, acc0b = 0ull, acc1a = 0ull, acc1b = 0ull;

        #pragma unroll
        for (int d = 0; d < 8; d++) {
            uint2 u = *reinterpret_cast<const uint2*>(wrow + d * 8);
            __half2 h0 = *reinterpret_cast<__half2*>(&u.x);
            __half2 h1 = *reinterpret_cast<__half2*>(&u.y);
            float2 f0 = __half22float2(h0);
            float2 f1 = __half22float2(h1);
            u64 wa = pack2(f0.x, f0.y);
            u64 wb = pack2(f1.x, f1.y);
            u64 xs0 = pack2(x0[d], x0[d]);
            u64 xs1 = pack2(x1[d], x1[d]);
            ffma2(acc0a, xs0, wa);
            ffma2(acc0b, xs0, wb);
            ffma2(acc1a, xs1, wa);
            ffma2(acc1b, xs1, wb);
        }

        asm("add.rn.f32x2 %0, %0, %1;" : "+l"(S0p[0]) : "l"(acc0a));
        asm("add.rn.f32x2 %0, %0, %1;" : "+l"(S0p[1]) : "l"(acc0b));
        asm("add.rn.f32x2 %0, %0, %1;" : "+l"(S0p[2]) : "l"(acc1a));
        asm("add.rn.f32x2 %0, %0, %1;" : "+l"(S0p[3]) : "l"(acc1b));

        // store x_hat fp16, pair-swizzled (pp = q ^ (i&3))
        {
            const int pp = q ^ rl3;
            float lo, hi;
            unsigned w0, w1;
            unpack2(acc0a, lo, hi);
            { __half2 h = __floats2half2_rn(lo, hi); w0 = *reinterpret_cast<unsigned*>(&h); }
            unpack2(acc0b, lo, hi);
            { __half2 h = __floats2half2_rn(lo, hi); w1 = *reinterpret_cast<unsigned*>(&h); }
            *reinterpret_cast<uint2*>(xhb + (i * 4 + bh * 2 + 0) * 8 + pp * 2) = make_uint2(w0, w1);
            unpack2(acc1a, lo, hi);
            { __half2 h = __floats2half2_rn(lo, hi); w0 = *reinterpret_cast<unsigned*>(&h); }
            unpack2(acc1b, lo, hi);
            { __half2 h = __floats2half2_rn(lo, hi); w1 = *reinterpret_cast<unsigned*>(&h); }
            *reinterpret_cast<uint2*>(xhb + (i * 4 + bh * 2 + 1) * 8 + pp * 2) = make_uint2(w0, w1);
        }
    }

    // ---- iter-0 reduction (build map) ----
    float* red = sm + OFF_RED;
    float* tot = sm + OFF_TOT;
    float* zt  = sm + OFF_ZT;
    float* vsm = sm + OFF_V;
    float* vss = sm + OFF_VS;

    {
        float s0[8];
        unpack2(S0p[0], s0[0], s0[1]);
        unpack2(S0p[1], s0[2], s0[3]);
        unpack2(S0p[2], s0[4], s0[5]);
        unpack2(S0p[3], s0[6], s0[7]);
        #pragma unroll
        for (int m = 8; m < 32; m <<= 1)
            #pragma unroll
            for (int e = 0; e < 8; e++)
                s0[e] += __shfl_xor_sync(0xffffffffu, s0[e], m);
        if (lane < 8) {                    // lane = q + 4*bh
            float* rp = red + warp * 64 + lane * 8;
            #pragma unroll
            for (int e = 0; e < 8; e++) rp[e] = s0[e];
        }
        __syncthreads();

        if (tid < 64) {
            const int bb = tid & 3, c = tid >> 2;
            const int cls = (c >> 2) + 4 * (bb >> 1);
            const int ele = (c & 3) + 4 * (bb & 1);
            float s = 0.f;
            #pragma unroll
            for (int w2 = 0; w2 < 16; w2++)
                s += red[w2 * 64 + cls * 8 + ele];
            tot[bb * 16 + c] = s;
        }
        __syncthreads();

        if (tid < BPC) {                   // squash iter 0 (Z = 1152 exactly)
            const int bb = tid;
            const float inv = 1.f / (float)ICAPS;
            float sv[16], n2 = 0.f;
            #pragma unroll
            for (int c = 0; c < 16; c++) {
                sv[c] = tot[bb * 16 + c] * inv;
                n2 += sv[c] * sv[c];
            }
            float nr = sqrtf(n2);
            float coef = (n2 / (1.f + n2)) / (nr + 1e-7f);
            #pragma unroll
            for (int c = 0; c < 16; c++) {
                float vn = coef * sv[c];
                vsm[bb * 16 + c] = vn;
                vss[bb * 16 + c] = vn;     // logits are linear in v: keep cumulative sum
            }
        }
        __syncthreads();
    }

    // ---- Routing iters 1,2: thread = (b = tid&3, r' = tid>>2) ----
    const int b2  = tid & 3;
    const int r2  = tid >> 2;
    const int sl3 = r2 & 3;

    #pragma unroll
    for (int it = 1; it < 3; it++) {
        float S[16];
        #pragma unroll
        for (int c = 0; c < 16; c++) S[c] = 0.f;
        float Zp = 0.f;
        float vv[16];
        #pragma unroll
        for (int c = 0; c < 16; c++) vv[c] = vss[b2 * 16 + c];

        #pragma unroll
        for (int rd = 0; rd < NRD2; rd++) {
            const int i = rd * 128 + r2;
            const unsigned base = (unsigned)((i * 4 + b2) * 8);
            float xf[16];
            #pragma unroll
            for (int qq = 0; qq < 4; qq++) {
                uint2 u = *reinterpret_cast<const uint2*>(xhb + base + (qq ^ sl3) * 2);
                __half2 h0 = *reinterpret_cast<__half2*>(&u.x);
                __half2 h1 = *reinterpret_cast<__half2*>(&u.y);
                float2 f0 = __half22float2(h0);
                float2 f1 = __half22float2(h1);
                xf[qq * 4 + 0] = f0.x; xf[qq * 4 + 1] = f0.y;
                xf[qq * 4 + 2] = f1.x; xf[qq * 4 + 3] = f1.y;
            }
            float a = 0.f;
            #pragma unroll
            for (int c = 0; c < 16; c++) a = fmaf(vv[c], xf[c], a);
            float e = __expf(a);           // a IS the logit (vsum . x_hat); |a| small
            Zp += e;
            #pragma unroll
            for (int c = 0; c < 16; c++) S[c] = fmaf(e, xf[c], S[c]);
        }

        #pragma unroll
        for (int m = 4; m < 32; m <<= 1) {
            #pragma unroll
            for (int c = 0; c < 16; c++)
                S[c] += __shfl_xor_sync(0xffffffffu, S[c], m);
            Zp += __shfl_xor_sync(0xffffffffu, Zp, m);
        }
        if (lane < 4) {
            float* rp = red + (warp * 4 + lane) * 17;
            #pragma unroll
            for (int c = 0; c < 16; c++) rp[c] = S[c];
            rp[16] = Zp;
        }
        __syncthreads();

        if (tid < 64) {
            const int bb = tid & 3, c = tid >> 2;
            float s = 0.f;
            #pragma unroll
            for (int w2 = 0; w2 < 16; w2++)
                s += red[(w2 * 4 + bb) * 17 + c];
            tot[bb * 16 + c] = s;
        } else if (tid < 68) {
            const int bb = tid - 64;
            float z = 0.f;
            #pragma unroll
            for (int w2 = 0; w2 < 16; w2++)
                z += red[(w2 * 4 + bb) * 17 + 16];
            zt[bb] = z;
        }
        __syncthreads();

        if (tid < BPC) {
            const int bb = tid;
            float inv = 1.f / zt[bb];
            float sv[16], n2 = 0.f;
            #pragma unroll
            for (int c = 0; c < 16; c++) {
                sv[c] = tot[bb * 16 + c] * inv;
                n2 += sv[c] * sv[c];
            }
            float nr = sqrtf(n2);
            float coef = (n2 / (1.f + n2)) / (nr + 1e-7f);
            #pragma unroll
            for (int c = 0; c < 16; c++) {
                float vn = coef * sv[c];
                vsm[bb * 16 + c] = vn;
                vss[bb * 16 + c] += vn;
            }
        }
        __syncthreads();
    }

    // ---- Output (B, J, C) ----
    if (tid < 64) {
        const int bb = tid >> 4, c = tid & 15;
        out[((size_t)(bg * BPC + bb) * JCAPS + j) * CDIM + c] = vsm[bb * 16 + c];
    }
}

extern "C" void kernel_launch(void* const* d_in, const int* in_sizes, int n_in,
                              void* d_out, int out_size)
{
    const float* x = (const float*)d_in[0];
    const float* W = (const float*)d_in[1];
    if (n_in >= 2 &&
        in_sizes[0] == JCAPS * ICAPS * DDIM * CDIM &&
        in_sizes[1] == BATCH * ICAPS * DDIM) {
        const float* t = x; x = W; W = t;
    }
    float* out = (float*)d_out;

    // Kernel A: W -> fp16 (10*1152*128 = 1,474,560 floats = 368,640 float4)
    convert_w_kernel<<<720, 512>>>(W);

    cudaFuncSetAttribute(digitcaps_kernel,
                         cudaFuncAttributeMaxDynamicSharedMemorySize,
                         SMEMF * (int)sizeof(float));
    dim3 grid((BATCH / BPC) * JCAPS);   // 1280 CTAs
    digitcaps_kernel<<<grid, TPB, SMEMF * sizeof(float)>>>(x, out);
}

// round 11
// speedup vs baseline: 2.8489x; 1.3553x over previous
#include <cuda_runtime.h>
#include <cuda_fp16.h>
#include <cstdint>
#include <cstddef>

// Problem dims
#define BATCH 512
#define ICAPS 1152
#define DDIM  8
#define JCAPS 10
#define CDIM  16

// Config. Build map: q = tid&3 (channel-quad), r = tid>>2 (row 0..127); 4 batches/thread.
#define TPB  512
#define BPC  4
#define ROWS 128           // W rows per round
#define NRD  9             // 1152 / 128
#define WRSH 72            // fp16-W smem row stride in floats (64 data + 8 pad)
#define WSZ1 (ROWS * WRSH) // 9216 floats per buffer

// Shared layout (float units)
#define OFF_W   0                      // 2 fp16-W buffers
#define OFF_XH  (2 * WSZ1)             // 18432 : x_hat rows (i*4 + b^(i&3)) x 8 u32, chunk-swizzled
#define XH_U32  (ICAPS * BPC * 8)      // 36864
#define OFF_RED (OFF_XH + XH_U32)      // 55296 : scratch (build 16*4*16 / routing 16*4*17)
#define OFF_TOT (OFF_RED + 1152)       // 56448 : [4][16]
#define OFF_ZT  (OFF_TOT + 64)         // 56512 : [4]
#define OFF_V   (OFF_ZT + 4)           // 56516 : v    [4][16]
#define OFF_VS  (OFF_V + 64)           // 56580 : vsum [4][16]
#define SMEMF   (OFF_VS + 64)          // 56644 floats = 226576 B

typedef unsigned long long u64;

__device__ __half2 g_Wh[JCAPS * ICAPS * CDIM * DDIM / 2];   // fp16 W scratch (2.95 MB)

__device__ __forceinline__ void cp16(float* dst, const void* src) {
    unsigned s = (unsigned)__cvta_generic_to_shared(dst);
    asm volatile("cp.async.cg.shared.global [%0], [%1], 16;" :: "r"(s), "l"(src));
}
__device__ __forceinline__ u64 pack2(float lo, float hi) {
    u64 r; asm("mov.b64 %0, {%1, %2};" : "=l"(r) : "f"(lo), "f"(hi)); return r;
}
__device__ __forceinline__ void unpack2(u64 v, float& lo, float& hi) {
    asm("mov.b64 {%0, %1}, %2;" : "=f"(lo), "=f"(hi) : "l"(v));
}
__device__ __forceinline__ void ffma2(u64& d, u64 a, u64 b) {
    asm("fma.rn.f32x2 %0, %1, %2, %0;" : "+l"(d) : "l"(a), "l"(b));
}
__device__ __forceinline__ unsigned h2_of(u64 acc) {
    float lo, hi; unpack2(acc, lo, hi);
    __half2 h = __floats2half2_rn(lo, hi);
    return *reinterpret_cast<unsigned*>(&h);
}

// ---- Kernel A: W fp32 -> fp16 ----
__global__ void __launch_bounds__(512, 4)
convert_w_kernel(const float* __restrict__ W)
{
    int i = blockIdx.x * 512 + threadIdx.x;   // float4 index, exact cover (368640)
    float4 f = reinterpret_cast<const float4*>(W)[i];
    g_Wh[i * 2 + 0] = __floats2half2_rn(f.x, f.y);
    g_Wh[i * 2 + 1] = __floats2half2_rn(f.z, f.w);
}

// ---- Kernel B: main ----
__global__ void __launch_bounds__(TPB, 1)
digitcaps_kernel(const float* __restrict__ x,
                 float* __restrict__ out)
{
    extern __shared__ float sm[];
    unsigned* xhb = reinterpret_cast<unsigned*>(sm + OFF_XH);

    const int tid  = threadIdx.x;
    const int j    = blockIdx.x % JCAPS;
    const int bg   = blockIdx.x / JCAPS;
    const int lane = tid & 31;
    const int warp = tid >> 5;

    // Build map
    const int q  = tid & 3;
    const int r  = tid >> 2;               // 0..127
    const int s3 = r & 3;                  // == i&3 for every round (128 % 4 == 0)

    const __half* Wjh = reinterpret_cast<const __half*>(g_Wh)
                      + (size_t)j * ICAPS * (DDIM * CDIM);
    const float* xg0 = x + ((size_t)bg * BPC + 0) * ICAPS * DDIM;
    const float* xg1 = x + ((size_t)bg * BPC + 1) * ICAPS * DDIM;
    const float* xg2 = x + ((size_t)bg * BPC + 2) * ICAPS * DDIM;
    const float* xg3 = x + ((size_t)bg * BPC + 3) * ICAPS * DDIM;

    // ---- Prologue: stage fp16 W round 0 (2048 16B chunks, 4/thread) ----
    #pragma unroll
    for (int k = 0; k < 4; k++) {
        int idx = k * TPB + tid;
        cp16(sm + OFF_W + (idx >> 4) * WRSH + (idx & 15) * 4, Wjh + (size_t)idx * 8);
    }
    asm volatile("cp.async.commit_group;");

    u64 S0p[8];                            // iter-0 S: [b][pair] f32x2
    #pragma unroll
    for (int k = 0; k < 8; k++) S0p[k] = 0ull;

    // ---- Build: 9 rounds, double-buffered fp16 W, 4 batches/thread ----
    #pragma unroll 1
    for (int rd = 0; rd < NRD; rd++) {
        asm volatile("cp.async.wait_group 0;");
        __syncthreads();                   // W[rd] visible; all past buffer rd-1

        const int i = rd * ROWS + r;

        // x rows for 4 batches (L2-resident LDG.128 x2 each)
        const float* px0 = xg0 + (size_t)i * DDIM;
        const float* px1 = xg1 + (size_t)i * DDIM;
        const float* px2 = xg2 + (size_t)i * DDIM;
        const float* px3 = xg3 + (size_t)i * DDIM;
        float4 a0 = *reinterpret_cast<const float4*>(px0);
        float4 b0 = *reinterpret_cast<const float4*>(px0 + 4);
        float4 a1 = *reinterpret_cast<const float4*>(px1);
        float4 b1 = *reinterpret_cast<const float4*>(px1 + 4);
        float4 a2 = *reinterpret_cast<const float4*>(px2);
        float4 b2 = *reinterpret_cast<const float4*>(px2 + 4);
        float4 a3 = *reinterpret_cast<const float4*>(px3);
        float4 b3 = *reinterpret_cast<const float4*>(px3 + 4);
        float xv0[8] = {a0.x,a0.y,a0.z,a0.w,b0.x,b0.y,b0.z,b0.w};
        float xv1[8] = {a1.x,a1.y,a1.z,a1.w,b1.x,b1.y,b1.z,b1.w};
        float xv2[8] = {a2.x,a2.y,a2.z,a2.w,b2.x,b2.y,b2.z,b2.w};
        float xv3[8] = {a3.x,a3.y,a3.z,a3.w,b3.x,b3.y,b3.z,b3.w};

        if (rd + 1 < NRD) {                // stage rd+1 into the other buffer
            const __half* wsrc = Wjh + (size_t)(rd + 1) * ROWS * (DDIM * CDIM);
            float* wd = sm + OFF_W + ((rd + 1) & 1) * WSZ1;
            #pragma unroll
            for (int k = 0; k < 4; k++) {
                int idx = k * TPB + tid;
                cp16(wd + (idx >> 4) * WRSH + (idx & 15) * 4, wsrc + (size_t)idx * 8);
            }
            asm volatile("cp.async.commit_group;");
        }

        // W dequant once, used by all 4 batches
        const float* wrow = sm + OFF_W + (rd & 1) * WSZ1 + r * WRSH + q * 2;
        u64 ac[8];                         // [b][pair]
        #pragma unroll
        for (int k = 0; k < 8; k++) ac[k] = 0ull;

        #pragma unroll
        for (int d = 0; d < 8; d++) {
            uint2 u = *reinterpret_cast<const uint2*>(wrow + d * 8);
            __half2 h0 = *reinterpret_cast<__half2*>(&u.x);
            __half2 h1 = *reinterpret_cast<__half2*>(&u.y);
            float2 f0 = __half22float2(h0);
            float2 f1 = __half22float2(h1);
            u64 wa = pack2(f0.x, f0.y);
            u64 wb = pack2(f1.x, f1.y);
            u64 xs0 = pack2(xv0[d], xv0[d]);
            u64 xs1 = pack2(xv1[d], xv1[d]);
            u64 xs2 = pack2(xv2[d], xv2[d]);
            u64 xs3 = pack2(xv3[d], xv3[d]);
            ffma2(ac[0], xs0, wa);  ffma2(ac[1], xs0, wb);
            ffma2(ac[2], xs1, wa);  ffma2(ac[3], xs1, wb);
            ffma2(ac[4], xs2, wa);  ffma2(ac[5], xs2, wb);
            ffma2(ac[6], xs3, wa);  ffma2(ac[7], xs3, wb);
        }

        #pragma unroll
        for (int k = 0; k < 8; k++)
            asm("add.rn.f32x2 %0, %0, %1;" : "+l"(S0p[k]) : "l"(ac[k]));

        // Store x_hat fp16: row (i*4 + (b^s3)), chunk (q^s3) -> both sides at bank floor
        {
            const unsigned wofs = (unsigned)((q ^ s3) * 2);
            #pragma unroll
            for (int b = 0; b < 4; b++) {
                unsigned row = (unsigned)(i * 4 + (b ^ s3));
                *reinterpret_cast<uint2*>(xhb + row * 8 + wofs) =
                    make_uint2(h2_of(ac[b * 2]), h2_of(ac[b * 2 + 1]));
            }
        }
    }

    // ---- iter-0 reduction (build map) ----
    float* red = sm + OFF_RED;
    float* tot = sm + OFF_TOT;
    float* zt  = sm + OFF_ZT;
    float* vsm = sm + OFF_V;
    float* vss = sm + OFF_VS;

    {
        float s0[16];                      // [b*4 + cc]
        #pragma unroll
        for (int b = 0; b < 4; b++) {
            unpack2(S0p[b * 2],     s0[b * 4 + 0], s0[b * 4 + 1]);
            unpack2(S0p[b * 2 + 1], s0[b * 4 + 2], s0[b * 4 + 3]);
        }
        #pragma unroll
        for (int m = 4; m < 32; m <<= 1)
            #pragma unroll
            for (int e = 0; e < 16; e++)
                s0[e] += __shfl_xor_sync(0xffffffffu, s0[e], m);
        if (lane < 4) {                    // lane == q class
            float* rp = red + (warp * 4 + lane) * 16;
            #pragma unroll
            for (int e = 0; e < 16; e++) rp[e] = s0[e];
        }
        __syncthreads();

        if (tid < 64) {
            const int bb = tid & 3, c = tid >> 2;
            float s = 0.f;
            #pragma unroll
            for (int w2 = 0; w2 < 16; w2++)
                s += red[(w2 * 4 + (c >> 2)) * 16 + bb * 4 + (c & 3)];
            tot[bb * 16 + c] = s;
        }
        __syncthreads();

        if (tid < BPC) {                   // squash iter 0 (Z = 1152 exactly)
            const int bb = tid;
            const float inv = 1.f / (float)ICAPS;
            float sv[16], n2 = 0.f;
            #pragma unroll
            for (int c = 0; c < 16; c++) {
                sv[c] = tot[bb * 16 + c] * inv;
                n2 += sv[c] * sv[c];
            }
            float nr = sqrtf(n2);
            float coef = (n2 / (1.f + n2)) / (nr + 1e-7f);
            #pragma unroll
            for (int c = 0; c < 16; c++) {
                float vn = coef * sv[c];
                vsm[bb * 16 + c] = vn;
                vss[bb * 16 + c] = vn;     // logits linear in v -> cumulative sum
            }
        }
        __syncthreads();
    }

    // ---- Routing iters 1,2: thread = (b2 = tid&3, r2 = tid>>2) ----
    const int b2  = tid & 3;
    const int r2  = tid >> 2;
    const int sl3 = r2 & 3;                // == i&3

    #pragma unroll
    for (int it = 1; it < 3; it++) {
        float S[16];
        #pragma unroll
        for (int c = 0; c < 16; c++) S[c] = 0.f;
        float Zp = 0.f;
        float vv[16];
        #pragma unroll
        for (int c = 0; c < 16; c++) vv[c] = vss[b2 * 16 + c];

        #pragma unroll
        for (int rd = 0; rd < NRD; rd++) {
            const int i = rd * 128 + r2;
            const unsigned base = (unsigned)((i * 4 + (b2 ^ sl3)) * 8);
            float xf[16];
            #pragma unroll
            for (int cc = 0; cc < 4; cc++) {
                uint2 u = *reinterpret_cast<const uint2*>(xhb + base + ((cc ^ sl3) * 2));
                __half2 h0 = *reinterpret_cast<__half2*>(&u.x);
                __half2 h1 = *reinterpret_cast<__half2*>(&u.y);
                float2 f0 = __half22float2(h0);
                float2 f1 = __half22float2(h1);
                xf[cc * 4 + 0] = f0.x; xf[cc * 4 + 1] = f0.y;
                xf[cc * 4 + 2] = f1.x; xf[cc * 4 + 3] = f1.y;
            }
            float a = 0.f;
            #pragma unroll
            for (int c = 0; c < 16; c++) a = fmaf(vv[c], xf[c], a);
            float e = __expf(a);           // a IS the logit (vsum . x_hat); |a| small
            Zp += e;
            #pragma unroll
            for (int c = 0; c < 16; c++) S[c] = fmaf(e, xf[c], S[c]);
        }

        #pragma unroll
        for (int m = 4; m < 32; m <<= 1) {
            #pragma unroll
            for (int c = 0; c < 16; c++)
                S[c] += __shfl_xor_sync(0xffffffffu, S[c], m);
            Zp += __shfl_xor_sync(0xffffffffu, Zp, m);
        }
        if (lane < 4) {
            float* rp = red + (warp * 4 + lane) * 17;
            #pragma unroll
            for (int c = 0; c < 16; c++) rp[c] = S[c];
            rp[16] = Zp;
        }
        __syncthreads();

        if (tid < 64) {
            const int bb = tid & 3, c = tid >> 2;
            float s = 0.f;
            #pragma unroll
            for (int w2 = 0; w2 < 16; w2++)
                s += red[(w2 * 4 + bb) * 17 + c];
            tot[bb * 16 + c] = s;
        } else if (tid < 68) {
            const int bb = tid - 64;
            float z = 0.f;
            #pragma unroll
            for (int w2 = 0; w2 < 16; w2++)
                z += red[(w2 * 4 + bb) * 17 + 16];
            zt[bb] = z;
        }
        __syncthreads();

        if (tid < BPC) {
            const int bb = tid;
            float inv = 1.f / zt[bb];
            float sv[16], n2 = 0.f;
            #pragma unroll
            for (int c = 0; c < 16; c++) {
                sv[c] = tot[bb * 16 + c] * inv;
                n2 += sv[c] * sv[c];
            }
            float nr = sqrtf(n2);
            float coef = (n2 / (1.f + n2)) / (nr + 1e-7f);
            #pragma unroll
            for (int c = 0; c < 16; c++) {
                float vn = coef * sv[c];
                vsm[bb * 16 + c] = vn;
                vss[bb * 16 + c] += vn;
            }
        }
        __syncthreads();
    }

    // ---- Output (B, J, C) ----
    if (tid < 64) {
        const int bb = tid >> 4, c = tid & 15;
        out[((size_t)(bg * BPC + bb) * JCAPS + j) * CDIM + c] = vsm[bb * 16 + c];
    }
}

extern "C" void kernel_launch(void* const* d_in, const int* in_sizes, int n_in,
                              void* d_out, int out_size)
{
    const float* x = (const float*)d_in[0];
    const float* W = (const float*)d_in[1];
    if (n_in >= 2 &&
        in_sizes[0] == JCAPS * ICAPS * DDIM * CDIM &&
        in_sizes[1] == BATCH * ICAPS * DDIM) {
        const float* t = x; x = W; W = t;
    }
    float* out = (float*)d_out;

    convert_w_kernel<<<720, 512>>>(W);     // 368640 float4 chunks

    cudaFuncSetAttribute(digitcaps_kernel,
                         cudaFuncAttributeMaxDynamicSharedMemorySize,
                         SMEMF * (int)sizeof(float));
    dim3 grid((BATCH / BPC) * JCAPS);      // 1280 CTAs
    digitcaps_kernel<<<grid, TPB, SMEMF * sizeof(float)>>>(x, out);
}